// round 12
// baseline (speedup 1.0000x reference)
// SpatialAttention — R12 resubmission (R10 kernel, cache-bust rev c).
#include <cuda_runtime.h>
#include <cuda_bf16.h>
#include <stdint.h>

#define NB  32
#define IDF 768
#define CDF 768
#define QL  1024
#define SL  128

// bf16 split scratch
__device__ __align__(128) __nv_bfloat16 g_w_hi[(size_t)IDF * CDF];
__device__ __align__(128) __nv_bfloat16 g_w_lo[(size_t)IDF * CDF];
__device__ __align__(128) __nv_bfloat16 g_ctxT_hi[(size_t)NB * SL * CDF];
__device__ __align__(128) __nv_bfloat16 g_ctxT_lo[(size_t)NB * SL * CDF];
__device__ __align__(128) __nv_bfloat16 g_sis_hi[(size_t)NB * IDF * SL];   // [b][i][s]
__device__ __align__(128) __nv_bfloat16 g_sis_lo[(size_t)NB * IDF * SL];
__device__ __align__(128) __nv_bfloat16 g_ssi_hi[(size_t)NB * SL * IDF];   // [b][s][i]
__device__ __align__(128) __nv_bfloat16 g_ssi_lo[(size_t)NB * SL * IDF];

__device__ __forceinline__ uint32_t smem_u32(const void* p) {
    uint32_t a;
    asm("{ .reg .u64 t; cvta.to.shared.u64 t, %1; cvt.u32.u64 %0, t; }" : "=r"(a) : "l"(p));
    return a;
}
#define SW64(x) ((x) ^ (((x) >> 3) & 0x30))

__device__ __forceinline__ void split2(float v, __nv_bfloat16& h, __nv_bfloat16& l) {
    h = __float2bfloat16(v);
    l = __float2bfloat16(v - __bfloat162float(h));
}
__device__ __forceinline__ uint32_t pack_bf2(__nv_bfloat16 a, __nv_bfloat16 b) {
    __nv_bfloat162 p; p.x = a; p.y = b;
    return *reinterpret_cast<uint32_t*>(&p);
}

#define CP_A16(dst, src) \
    asm volatile("cp.async.cg.shared.global [%0], [%1], 16;" :: "r"(dst), "l"(src))
#define CP_COMMIT() asm volatile("cp.async.commit_group;" ::: "memory")
#define CP_WAIT0()  asm volatile("cp.async.wait_group 0;" ::: "memory")
#define CP_WAIT1()  asm volatile("cp.async.wait_group 1;" ::: "memory")

// k=32 bf16 K-major tile [ROWS x 64B], SW64-swizzled, via cp.async. gstride bytes.
template <int ROWS>
__device__ __forceinline__ void cp64(uint32_t sbase, const __nv_bfloat16* g,
                                     int gstride, int tid) {
#pragma unroll
    for (int p = 0; p < ROWS / 64; p++) {
        int idx = tid + p * 256;
        int row = idx >> 2, c = (idx & 3) << 4;
        CP_A16(sbase + SW64((uint32_t)(row * 64 + c)),
               reinterpret_cast<const char*>(g) + (size_t)row * gstride + c);
    }
}

// x4 ldmatrix of a 16x16 bf16 block at (row0, kbyte) in a SW64 [r][64B] tile.
__device__ __forceinline__ void ldm4_64(uint32_t r[4], uint32_t base, int row0,
                                        int kbyte, int lane) {
    int row = row0 + (lane & 15);
    int col = kbyte + ((lane >> 4) << 4);
    uint32_t addr = base + SW64((uint32_t)(row * 64 + col));
    asm volatile("ldmatrix.sync.aligned.m8n8.x4.shared.b16 {%0,%1,%2,%3}, [%4];"
                 : "=r"(r[0]), "=r"(r[1]), "=r"(r[2]), "=r"(r[3]) : "r"(addr));
}

__device__ __forceinline__ void mma16(float c[4], const uint32_t a[4], const uint32_t b[2]) {
    asm volatile("mma.sync.aligned.m16n8k16.row.col.f32.bf16.bf16.f32 "
                 "{%0,%1,%2,%3}, {%4,%5,%6,%7}, {%8,%9}, {%0,%1,%2,%3};"
                 : "+f"(c[0]), "+f"(c[1]), "+f"(c[2]), "+f"(c[3])
                 : "r"(a[0]), "r"(a[1]), "r"(a[2]), "r"(a[3]), "r"(b[0]), "r"(b[1]));
}

// One k=32 chunk of a 32(m) x 32(n) warp tile, split-bf16 (3 mmas per pair).
__device__ __forceinline__ void gemm_chunk(float acc[2][4][4],
                                           uint32_t aHi, uint32_t aLo,
                                           uint32_t bHi, uint32_t bLo,
                                           int m0, int n0, int lane) {
#pragma unroll
    for (int k = 0; k < 2; k++) {
        const int kb = k * 32;
        uint32_t ah[2][4], al[2][4], bh[4][2], bl[4][2], t[4];
#pragma unroll
        for (int m = 0; m < 2; m++) {
            ldm4_64(ah[m], aHi, m0 + m * 16, kb, lane);
            ldm4_64(al[m], aLo, m0 + m * 16, kb, lane);
        }
#pragma unroll
        for (int j = 0; j < 2; j++) {
            ldm4_64(t, bHi, n0 + j * 16, kb, lane);
            bh[2 * j][0] = t[0]; bh[2 * j][1] = t[2];
            bh[2 * j + 1][0] = t[1]; bh[2 * j + 1][1] = t[3];
            ldm4_64(t, bLo, n0 + j * 16, kb, lane);
            bl[2 * j][0] = t[0]; bl[2 * j][1] = t[2];
            bl[2 * j + 1][0] = t[1]; bl[2 * j + 1][1] = t[3];
        }
#pragma unroll
        for (int m = 0; m < 2; m++)
#pragma unroll
            for (int n = 0; n < 4; n++) {
                mma16(acc[m][n], ah[m], bh[n]);
                mma16(acc[m][n], ah[m], bl[n]);
                mma16(acc[m][n], al[m], bh[n]);
            }
    }
}

#define ZERO_ACC(acc) \
    { _Pragma("unroll") for (int m = 0; m < 2; m++) \
      _Pragma("unroll") for (int n = 0; n < 4; n++) \
      _Pragma("unroll") for (int v = 0; v < 4; v++) acc[m][n][v] = 0.f; }

#define PSTAGE 24576
#define BSTAGE 16384
#define NSTG   3

// attn smem layout (bytes from base):
//   [0, 49152)        3 x 16KB B stage slots (phase 1: ssi, phase 3: sis)
//   [49152, 82176)    Cb fp32 64x129 (phase-1 A-slots 3x8KB alias its first 24KB)
//   [82176, 114944)   BATT: 4 s-chunks x (hi 4KB | lo 4KB)
#define CBOFF  49152
#define BATTOFF 82176
#define ATTN_SMEM 114944

// ---------------- small pre-pass kernels ----------------
__global__ void conv_w_kernel(const float* __restrict__ w) {
    int i4 = blockIdx.x * 256 + threadIdx.x;
    float4 v = reinterpret_cast<const float4*>(w)[i4];
    __nv_bfloat16 h0, l0, h1, l1, h2, l2, h3, l3;
    split2(v.x, h0, l0); split2(v.y, h1, l1); split2(v.z, h2, l2); split2(v.w, h3, l3);
    reinterpret_cast<uint2*>(g_w_hi)[i4] = make_uint2(pack_bf2(h0, h1), pack_bf2(h2, h3));
    reinterpret_cast<uint2*>(g_w_lo)[i4] = make_uint2(pack_bf2(l0, l1), pack_bf2(l2, l3));
}

__global__ void trans_ctx_kernel(const float* __restrict__ in) {   // [b][c][s]->[b][s][c]
    __shared__ float t[32][33];
    int b = blockIdx.z, c0 = blockIdx.y * 32, s0 = blockIdx.x * 32;
    int x = threadIdx.x, y = threadIdx.y;
#pragma unroll
    for (int r = 0; r < 32; r += 8)
        t[y + r][x] = in[((size_t)b * CDF + c0 + y + r) * SL + s0 + x];
    __syncthreads();
#pragma unroll
    for (int r = 0; r < 32; r += 8) {
        size_t o = ((size_t)b * SL + s0 + y + r) * CDF + c0 + x;
        __nv_bfloat16 h, l; split2(t[x][y + r], h, l);
        g_ctxT_hi[o] = h; g_ctxT_lo[o] = l;
    }
}

// ---------------- proj: srcT[b,o,s] = sum_c w[o,c]*ctx[b,c,s], 3-stage ----------------
__global__ void __launch_bounds__(256, 2) proj_kernel() {
    extern __shared__ __align__(1024) char smem[];
    const int tid = threadIdx.x;
    const int lane = tid & 31, wp = tid >> 5;
    const int wm = wp & 1, wn = wp >> 1;                     // D 64(o) x 128(s)
    const int b = blockIdx.y, o0 = blockIdx.x * 64;
    uint32_t sb = smem_u32(smem);
    float* Cb = reinterpret_cast<float*>(smem);

    const __nv_bfloat16* wh_base = g_w_hi + (size_t)o0 * CDF;
    const __nv_bfloat16* wl_base = g_w_lo + (size_t)o0 * CDF;
    const __nv_bfloat16* ch_base = g_ctxT_hi + (size_t)b * SL * CDF;
    const __nv_bfloat16* cl_base = g_ctxT_lo + (size_t)b * SL * CDF;

    float acc[2][4][4];
    ZERO_ACC(acc);

    auto issue = [&](int j) {
        uint32_t S = sb + (j % NSTG) * PSTAGE;
        cp64<64>(S,          wh_base + j * 32, CDF * 2, tid);
        cp64<64>(S + 4096,   wl_base + j * 32, CDF * 2, tid);
        cp64<128>(S + 8192,  ch_base + j * 32, CDF * 2, tid);
        cp64<128>(S + 16384, cl_base + j * 32, CDF * 2, tid);
        CP_COMMIT();
    };
    issue(0); issue(1);
#pragma unroll 1
    for (int j = 0; j < 24; j++) {
        if (j < 23) CP_WAIT1(); else CP_WAIT0();
        __syncthreads();
        if (j + 2 < 24) issue(j + 2);
        uint32_t S = sb + (j % NSTG) * PSTAGE;
        gemm_chunk(acc, S, S + 4096, S + 8192, S + 16384, wm * 32, wn * 32, lane);
    }
    __syncthreads();
#pragma unroll
    for (int m = 0; m < 2; m++)
#pragma unroll
        for (int n = 0; n < 4; n++) {
            int r = wm * 32 + m * 16 + (lane >> 2);
            int c = wn * 32 + n * 8 + (lane & 3) * 2;
            Cb[r * 129 + c]           = acc[m][n][0];
            Cb[r * 129 + c + 1]       = acc[m][n][1];
            Cb[(r + 8) * 129 + c]     = acc[m][n][2];
            Cb[(r + 8) * 129 + c + 1] = acc[m][n][3];
        }
    __syncthreads();

    // sis [b][i][s]: thread -> (o = tid/4, 32 s)
    {
        const int o = tid >> 2, sq = (tid & 3) * 32;
        uint32_t uh[16], ul[16];
#pragma unroll
        for (int m = 0; m < 16; m++) {
            float v0 = Cb[o * 129 + sq + 2 * m];
            float v1 = Cb[o * 129 + sq + 2 * m + 1];
            __nv_bfloat16 h0, l0, h1, l1; split2(v0, h0, l0); split2(v1, h1, l1);
            uh[m] = pack_bf2(h0, h1); ul[m] = pack_bf2(l0, l1);
        }
        size_t off = ((size_t)b * IDF + o0 + o) * SL + sq;
#pragma unroll
        for (int m = 0; m < 4; m++) {
            reinterpret_cast<uint4*>(g_sis_hi + off)[m] =
                make_uint4(uh[4 * m], uh[4 * m + 1], uh[4 * m + 2], uh[4 * m + 3]);
            reinterpret_cast<uint4*>(g_sis_lo + off)[m] =
                make_uint4(ul[4 * m], ul[4 * m + 1], ul[4 * m + 2], ul[4 * m + 3]);
        }
    }
    // ssi [b][s][i]: thread -> (s = tid/2, 32 o)
    {
        const int s = tid >> 1, oq = (tid & 1) * 32;
        uint32_t uh[16], ul[16];
#pragma unroll
        for (int m = 0; m < 16; m++) {
            float v0 = Cb[(oq + 2 * m) * 129 + s];
            float v1 = Cb[(oq + 2 * m + 1) * 129 + s];
            __nv_bfloat16 h0, l0, h1, l1; split2(v0, h0, l0); split2(v1, h1, l1);
            uh[m] = pack_bf2(h0, h1); ul[m] = pack_bf2(l0, l1);
        }
        size_t off = ((size_t)b * SL + s) * IDF + o0 + oq;
#pragma unroll
        for (int m = 0; m < 4; m++) {
            reinterpret_cast<uint4*>(g_ssi_hi + off)[m] =
                make_uint4(uh[4 * m], uh[4 * m + 1], uh[4 * m + 2], uh[4 * m + 3]);
            reinterpret_cast<uint4*>(g_ssi_lo + off)[m] =
                make_uint4(ul[4 * m], ul[4 * m + 1], ul[4 * m + 2], ul[4 * m + 3]);
        }
    }
}

// ---------------- fused attention: dedicated Cb, attn_out overlapped into phase 3 ----------------
__global__ void __launch_bounds__(256, 2) attn_kernel(const float* __restrict__ input,
                                                      const int* __restrict__ mask,
                                                      float* __restrict__ wc,
                                                      float* __restrict__ aout) {
    extern __shared__ __align__(1024) char smem[];
    __shared__ float mpen[SL];
    const int tid = threadIdx.x;
    const int lane = tid & 31, wp = tid >> 5;
    const int b = blockIdx.y, q0 = blockIdx.x * 64;
    uint32_t sb = smem_u32(smem);
    const uint32_t ASLOT = sb + CBOFF;              // 3 x 8KB, aliases Cb (dead then)
    const uint32_t BATT  = sb + BATTOFF;            // 4 s-chunks x (hi 4KB | lo 4KB)
    float* Cb = reinterpret_cast<float*>(smem + CBOFF);

    if (tid < SL) mpen[tid] = -10000.0f * (float)mask[b * SL + tid];

    // ---- phase 1: logits[q][s], K=768, 24 k=32 chunks ----
    const int wm1 = wp & 1, wn1 = wp >> 1;          // D 64(q) x 128(s)
    const __nv_bfloat16* sh_base = g_ssi_hi + (size_t)b * SL * IDF;
    const __nv_bfloat16* sl_base = g_ssi_lo + (size_t)b * SL * IDF;
    const int cq = tid & 63, cig = tid >> 6;        // conversion role
    const float* cbase = input + ((size_t)b * IDF + cig * 8) * QL + q0 + cq;
    const uint32_t coff = SW64((uint32_t)(cq * 64 + cig * 16));

    float acc[2][4][4];
    ZERO_ACC(acc);
    float cvt[8];

    auto ldgA = [&](int j) {
        const float* s = cbase + (size_t)(j * 32) * QL;
#pragma unroll
        for (int m = 0; m < 8; m++) cvt[m] = s[(size_t)m * QL];
    };
    auto stsA = [&](int j) {
        uint32_t h[4], l[4];
#pragma unroll
        for (int m = 0; m < 4; m++) {
            __nv_bfloat16 h0, l0, h1, l1;
            split2(cvt[2 * m], h0, l0); split2(cvt[2 * m + 1], h1, l1);
            h[m] = pack_bf2(h0, h1); l[m] = pack_bf2(l0, l1);
        }
        uint32_t A = ASLOT + (j % 3) * 8192;
        asm volatile("st.shared.v4.b32 [%0], {%1,%2,%3,%4};"
                     :: "r"(A + coff), "r"(h[0]), "r"(h[1]), "r"(h[2]), "r"(h[3]));
        asm volatile("st.shared.v4.b32 [%0], {%1,%2,%3,%4};"
                     :: "r"(A + 4096 + coff), "r"(l[0]), "r"(l[1]), "r"(l[2]), "r"(l[3]));
    };
    auto issueB = [&](int j) {
        uint32_t S = sb + (j % NSTG) * BSTAGE;
        cp64<128>(S,        sh_base + j * 32, IDF * 2, tid);
        cp64<128>(S + 8192, sl_base + j * 32, IDF * 2, tid);
        CP_COMMIT();
    };

    ldgA(0); stsA(0); ldgA(1);
    issueB(0); issueB(1);
#pragma unroll 1
    for (int j = 0; j < 24; j++) {
        if (j + 1 < 24) stsA(j + 1);
        if (j + 2 < 24) ldgA(j + 2);
        if (j < 23) CP_WAIT1(); else CP_WAIT0();
        __syncthreads();
        if (j + 2 < 24) issueB(j + 2);
        uint32_t S = sb + (j % NSTG) * BSTAGE;
        uint32_t A = ASLOT + (j % 3) * 8192;
        gemm_chunk(acc, A, A + 4096, S, S + 8192, wm1 * 32, wn1 * 32, lane);
    }
    __syncthreads();                                 // A-slots dead; Cb may be written
#pragma unroll
    for (int m = 0; m < 2; m++)
#pragma unroll
        for (int n = 0; n < 4; n++) {
            int r = wm1 * 32 + m * 16 + (lane >> 2);
            int c = wn1 * 32 + n * 8 + (lane & 3) * 2;
            Cb[r * 129 + c]           = acc[m][n][0];
            Cb[r * 129 + c + 1]       = acc[m][n][1];
            Cb[(r + 8) * 129 + c]     = acc[m][n][2];
            Cb[(r + 8) * 129 + c + 1] = acc[m][n][3];
        }
    __syncthreads();

    // ---- phase 2: softmax over s (4 threads/q-row); BATT gets bf16 split ----
    {
        const int q = tid >> 2, qa = tid & 3;
        float* row = Cb + q * 129 + qa * 32;
        const float* mp = mpen + qa * 32;
        float mx = -1e30f;
#pragma unroll
        for (int s = 0; s < 32; s++) {
            float x = row[s] + mp[s];
            row[s] = x;
            mx = fmaxf(mx, x);
        }
        mx = fmaxf(mx, __shfl_xor_sync(0xffffffffu, mx, 1));
        mx = fmaxf(mx, __shfl_xor_sync(0xffffffffu, mx, 2));
        float sum = 0.f;
#pragma unroll
        for (int s = 0; s < 32; s++) {
            float e = __expf(row[s] - mx);
            row[s] = e;
            sum += e;
        }
        sum += __shfl_xor_sync(0xffffffffu, sum, 1);
        sum += __shfl_xor_sync(0xffffffffu, sum, 2);
        const float inv = 1.0f / sum;
        const uint32_t BH = BATT + qa * 8192, BL = BH + 4096;
#pragma unroll
        for (int s = 0; s < 32; s += 2) {
            float a0 = row[s] * inv, a1 = row[s + 1] * inv;
            row[s] = a0; row[s + 1] = a1;
            __nv_bfloat16 h0, l0, h1, l1; split2(a0, h0, l0); split2(a1, h1, l1);
            uint32_t off = SW64((uint32_t)(q * 64 + s * 2));
            asm volatile("st.shared.b32 [%0], %1;" :: "r"(BH + off), "r"(pack_bf2(h0, h1)));
            asm volatile("st.shared.b32 [%0], %1;" :: "r"(BL + off), "r"(pack_bf2(l0, l1)));
        }
    }
    __syncthreads();   // BATT + normalized Cb visible to all

    // ---- phase 3: wc[i][q] = sum_s sis[i][s]*attn[q][s]; 6 tiles x 4 chunks.
    //      attn_out store interleaved into the first 16 iterations. ----
    const int wm3 = wp >> 1, wn3 = wp & 1;          // D 128(i) x 64(q)
    const __nv_bfloat16* sish_base = g_sis_hi + (size_t)b * IDF * SL;
    const __nv_bfloat16* sisl_base = g_sis_lo + (size_t)b * IDF * SL;
    float* ao = aout + (size_t)b * SL * QL + q0;
    const int ao_s0 = tid >> 5, ao_q = (tid & 31) * 2;
    auto issue3 = [&](int c) {
        int t = c >> 2, kc = c & 3;
        uint32_t S = sb + (c % NSTG) * BSTAGE;
        const size_t base = (size_t)t * 128 * SL + kc * 32;
        cp64<128>(S,        sish_base + base, SL * 2, tid);
        cp64<128>(S + 8192, sisl_base + base, SL * 2, tid);
        CP_COMMIT();
    };
    issue3(0); issue3(1);
#pragma unroll 1
    for (int c = 0; c < 24; c++) {
        if (c < 23) CP_WAIT1(); else CP_WAIT0();
        __syncthreads();
        if (c + 2 < 24) issue3(c + 2);
        if (c < 16) {                               // 8 attn_out rows per iter
            int s = c * 8 + ao_s0;
            float2 v = make_float2(Cb[ao_q * 129 + s], Cb[(ao_q + 1) * 129 + s]);
            *reinterpret_cast<float2*>(ao + (size_t)s * QL + ao_q) = v;
        }
        if ((c & 3) == 0) ZERO_ACC(acc);
        uint32_t S = sb + (c % NSTG) * BSTAGE;
        uint32_t BH = BATT + (c & 3) * 8192;
        gemm_chunk(acc, S, S + 8192, BH, BH + 4096, wm3 * 32, wn3 * 32, lane);
        if ((c & 3) == 3) {
            int t = c >> 2;
            float* w0 = wc + ((size_t)b * IDF + t * 128) * QL + q0;
#pragma unroll
            for (int m = 0; m < 2; m++)
#pragma unroll
                for (int n = 0; n < 4; n++) {
                    int r = wm3 * 32 + m * 16 + (lane >> 2);
                    int cc = wn3 * 32 + n * 8 + (lane & 3) * 2;
                    *reinterpret_cast<float2*>(w0 + (size_t)r * QL + cc) =
                        make_float2(acc[m][n][0], acc[m][n][1]);
                    *reinterpret_cast<float2*>(w0 + (size_t)(r + 8) * QL + cc) =
                        make_float2(acc[m][n][2], acc[m][n][3]);
                }
        }
    }
}

// ---------------------------------------------------------------------------
extern "C" void kernel_launch(void* const* d_in, const int* in_sizes, int n_in,
                              void* d_out, int out_size) {
    const float* input   = (const float*)d_in[0];
    const float* context = (const float*)d_in[1];
    const int*   mask    = (const int*)d_in[2];
    const float* w_conv  = (const float*)d_in[3];

    float* wc   = (float*)d_out;
    float* aout = wc + (size_t)NB * IDF * QL;

    conv_w_kernel<<<IDF * CDF / 4 / 256, 256>>>(w_conv);
    trans_ctx_kernel<<<dim3(SL / 32, CDF / 32, NB), dim3(32, 8)>>>(context);

    const int smem_proj = NSTG * PSTAGE;                    // 73728
    cudaFuncSetAttribute(proj_kernel, cudaFuncAttributeMaxDynamicSharedMemorySize,
                         smem_proj);
    proj_kernel<<<dim3(IDF / 64, NB), 256, smem_proj>>>();

    cudaFuncSetAttribute(attn_kernel, cudaFuncAttributeMaxDynamicSharedMemorySize,
                         ATTN_SMEM);                        // 114944
    attn_kernel<<<dim3(QL / 64, NB), 256, ATTN_SMEM>>>(input, mask, wc, aout);
}

// round 13
// speedup vs baseline: 1.2231x; 1.2231x over previous
// SpatialAttention — R13: register-resident softmax, no Cb in attn (smem = R9 level).
#include <cuda_runtime.h>
#include <cuda_bf16.h>
#include <stdint.h>

#define NB  32
#define IDF 768
#define CDF 768
#define QL  1024
#define SL  128

// bf16 split scratch
__device__ __align__(128) __nv_bfloat16 g_w_hi[(size_t)IDF * CDF];
__device__ __align__(128) __nv_bfloat16 g_w_lo[(size_t)IDF * CDF];
__device__ __align__(128) __nv_bfloat16 g_ctxT_hi[(size_t)NB * SL * CDF];
__device__ __align__(128) __nv_bfloat16 g_ctxT_lo[(size_t)NB * SL * CDF];
__device__ __align__(128) __nv_bfloat16 g_sis_hi[(size_t)NB * IDF * SL];   // [b][i][s]
__device__ __align__(128) __nv_bfloat16 g_sis_lo[(size_t)NB * IDF * SL];
__device__ __align__(128) __nv_bfloat16 g_ssi_hi[(size_t)NB * SL * IDF];   // [b][s][i]
__device__ __align__(128) __nv_bfloat16 g_ssi_lo[(size_t)NB * SL * IDF];

__device__ __forceinline__ uint32_t smem_u32(const void* p) {
    uint32_t a;
    asm("{ .reg .u64 t; cvta.to.shared.u64 t, %1; cvt.u32.u64 %0, t; }" : "=r"(a) : "l"(p));
    return a;
}
#define SW64(x) ((x) ^ (((x) >> 3) & 0x30))

__device__ __forceinline__ void split2(float v, __nv_bfloat16& h, __nv_bfloat16& l) {
    h = __float2bfloat16(v);
    l = __float2bfloat16(v - __bfloat162float(h));
}
__device__ __forceinline__ uint32_t pack_bf2(__nv_bfloat16 a, __nv_bfloat16 b) {
    __nv_bfloat162 p; p.x = a; p.y = b;
    return *reinterpret_cast<uint32_t*>(&p);
}

#define CP_A16(dst, src) \
    asm volatile("cp.async.cg.shared.global [%0], [%1], 16;" :: "r"(dst), "l"(src))
#define CP_COMMIT() asm volatile("cp.async.commit_group;" ::: "memory")
#define CP_WAIT0()  asm volatile("cp.async.wait_group 0;" ::: "memory")
#define CP_WAIT1()  asm volatile("cp.async.wait_group 1;" ::: "memory")

// k=32 bf16 K-major tile [ROWS x 64B], SW64-swizzled, via cp.async. gstride bytes.
template <int ROWS>
__device__ __forceinline__ void cp64(uint32_t sbase, const __nv_bfloat16* g,
                                     int gstride, int tid) {
#pragma unroll
    for (int p = 0; p < ROWS / 64; p++) {
        int idx = tid + p * 256;
        int row = idx >> 2, c = (idx & 3) << 4;
        CP_A16(sbase + SW64((uint32_t)(row * 64 + c)),
               reinterpret_cast<const char*>(g) + (size_t)row * gstride + c);
    }
}

// x4 ldmatrix of a 16x16 bf16 block at (row0, kbyte) in a SW64 [r][64B] tile.
__device__ __forceinline__ void ldm4_64(uint32_t r[4], uint32_t base, int row0,
                                        int kbyte, int lane) {
    int row = row0 + (lane & 15);
    int col = kbyte + ((lane >> 4) << 4);
    uint32_t addr = base + SW64((uint32_t)(row * 64 + col));
    asm volatile("ldmatrix.sync.aligned.m8n8.x4.shared.b16 {%0,%1,%2,%3}, [%4];"
                 : "=r"(r[0]), "=r"(r[1]), "=r"(r[2]), "=r"(r[3]) : "r"(addr));
}

__device__ __forceinline__ void mma16(float c[4], const uint32_t a[4], const uint32_t b[2]) {
    asm volatile("mma.sync.aligned.m16n8k16.row.col.f32.bf16.bf16.f32 "
                 "{%0,%1,%2,%3}, {%4,%5,%6,%7}, {%8,%9}, {%0,%1,%2,%3};"
                 : "+f"(c[0]), "+f"(c[1]), "+f"(c[2]), "+f"(c[3])
                 : "r"(a[0]), "r"(a[1]), "r"(a[2]), "r"(a[3]), "r"(b[0]), "r"(b[1]));
}

// One k=32 chunk of a 32(m) x 32(n) warp tile, split-bf16 (3 mmas per pair).
__device__ __forceinline__ void gemm_chunk(float acc[2][4][4],
                                           uint32_t aHi, uint32_t aLo,
                                           uint32_t bHi, uint32_t bLo,
                                           int m0, int n0, int lane) {
#pragma unroll
    for (int k = 0; k < 2; k++) {
        const int kb = k * 32;
        uint32_t ah[2][4], al[2][4], bh[4][2], bl[4][2], t[4];
#pragma unroll
        for (int m = 0; m < 2; m++) {
            ldm4_64(ah[m], aHi, m0 + m * 16, kb, lane);
            ldm4_64(al[m], aLo, m0 + m * 16, kb, lane);
        }
#pragma unroll
        for (int j = 0; j < 2; j++) {
            ldm4_64(t, bHi, n0 + j * 16, kb, lane);
            bh[2 * j][0] = t[0]; bh[2 * j][1] = t[2];
            bh[2 * j + 1][0] = t[1]; bh[2 * j + 1][1] = t[3];
            ldm4_64(t, bLo, n0 + j * 16, kb, lane);
            bl[2 * j][0] = t[0]; bl[2 * j][1] = t[2];
            bl[2 * j + 1][0] = t[1]; bl[2 * j + 1][1] = t[3];
        }
#pragma unroll
        for (int m = 0; m < 2; m++)
#pragma unroll
            for (int n = 0; n < 4; n++) {
                mma16(acc[m][n], ah[m], bh[n]);
                mma16(acc[m][n], ah[m], bl[n]);
                mma16(acc[m][n], al[m], bh[n]);
            }
    }
}

#define ZERO_ACC(acc) \
    { _Pragma("unroll") for (int m = 0; m < 2; m++) \
      _Pragma("unroll") for (int n = 0; n < 4; n++) \
      _Pragma("unroll") for (int v = 0; v < 4; v++) acc[m][n][v] = 0.f; }

#define PSTAGE 24576
#define BSTAGE 16384
#define NSTG   3
// attn smem: [0,49152) 3x16KB stages; [49152,73728) 3x8KB A-slots; [73728,106496) BATT
#define ASLOTOFF 49152
#define BATTOFF  73728
#define ATTN_SMEM 106496

// ---------------- small pre-pass kernels ----------------
__global__ void conv_w_kernel(const float* __restrict__ w) {
    int i4 = blockIdx.x * 256 + threadIdx.x;
    float4 v = reinterpret_cast<const float4*>(w)[i4];
    __nv_bfloat16 h0, l0, h1, l1, h2, l2, h3, l3;
    split2(v.x, h0, l0); split2(v.y, h1, l1); split2(v.z, h2, l2); split2(v.w, h3, l3);
    reinterpret_cast<uint2*>(g_w_hi)[i4] = make_uint2(pack_bf2(h0, h1), pack_bf2(h2, h3));
    reinterpret_cast<uint2*>(g_w_lo)[i4] = make_uint2(pack_bf2(l0, l1), pack_bf2(l2, l3));
}

__global__ void trans_ctx_kernel(const float* __restrict__ in) {   // [b][c][s]->[b][s][c]
    __shared__ float t[32][33];
    int b = blockIdx.z, c0 = blockIdx.y * 32, s0 = blockIdx.x * 32;
    int x = threadIdx.x, y = threadIdx.y;
#pragma unroll
    for (int r = 0; r < 32; r += 8)
        t[y + r][x] = in[((size_t)b * CDF + c0 + y + r) * SL + s0 + x];
    __syncthreads();
#pragma unroll
    for (int r = 0; r < 32; r += 8) {
        size_t o = ((size_t)b * SL + s0 + y + r) * CDF + c0 + x;
        __nv_bfloat16 h, l; split2(t[x][y + r], h, l);
        g_ctxT_hi[o] = h; g_ctxT_lo[o] = l;
    }
}

// ---------------- proj: srcT[b,o,s] = sum_c w[o,c]*ctx[b,c,s], 3-stage ----------------
__global__ void __launch_bounds__(256, 2) proj_kernel() {
    extern __shared__ __align__(1024) char smem[];
    const int tid = threadIdx.x, lane = tid & 31, wp = tid >> 5;
    const int wm = wp & 1, wn = wp >> 1;                     // D 64(o) x 128(s)
    const int b = blockIdx.y, o0 = blockIdx.x * 64;
    uint32_t sb = smem_u32(smem);
    float* Cb = reinterpret_cast<float*>(smem);

    const __nv_bfloat16* wh_base = g_w_hi + (size_t)o0 * CDF;
    const __nv_bfloat16* wl_base = g_w_lo + (size_t)o0 * CDF;
    const __nv_bfloat16* ch_base = g_ctxT_hi + (size_t)b * SL * CDF;
    const __nv_bfloat16* cl_base = g_ctxT_lo + (size_t)b * SL * CDF;

    float acc[2][4][4];
    ZERO_ACC(acc);

    auto issue = [&](int j) {
        uint32_t S = sb + (j % NSTG) * PSTAGE;
        cp64<64>(S,          wh_base + j * 32, CDF * 2, tid);
        cp64<64>(S + 4096,   wl_base + j * 32, CDF * 2, tid);
        cp64<128>(S + 8192,  ch_base + j * 32, CDF * 2, tid);
        cp64<128>(S + 16384, cl_base + j * 32, CDF * 2, tid);
        CP_COMMIT();
    };
    issue(0); issue(1);
#pragma unroll 1
    for (int j = 0; j < 24; j++) {
        if (j < 23) CP_WAIT1(); else CP_WAIT0();
        __syncthreads();
        if (j + 2 < 24) issue(j + 2);
        uint32_t S = sb + (j % NSTG) * PSTAGE;
        gemm_chunk(acc, S, S + 4096, S + 8192, S + 16384, wm * 32, wn * 32, lane);
    }
    __syncthreads();
#pragma unroll
    for (int m = 0; m < 2; m++)
#pragma unroll
        for (int n = 0; n < 4; n++) {
            int r = wm * 32 + m * 16 + (lane >> 2);
            int c = wn * 32 + n * 8 + (lane & 3) * 2;
            Cb[r * 129 + c]           = acc[m][n][0];
            Cb[r * 129 + c + 1]       = acc[m][n][1];
            Cb[(r + 8) * 129 + c]     = acc[m][n][2];
            Cb[(r + 8) * 129 + c + 1] = acc[m][n][3];
        }
    __syncthreads();

    // sis [b][i][s]: thread -> (o = tid/4, 32 s)
    {
        const int o = tid >> 2, sq = (tid & 3) * 32;
        uint32_t uh[16], ul[16];
#pragma unroll
        for (int m = 0; m < 16; m++) {
            float v0 = Cb[o * 129 + sq + 2 * m];
            float v1 = Cb[o * 129 + sq + 2 * m + 1];
            __nv_bfloat16 h0, l0, h1, l1; split2(v0, h0, l0); split2(v1, h1, l1);
            uh[m] = pack_bf2(h0, h1); ul[m] = pack_bf2(l0, l1);
        }
        size_t off = ((size_t)b * IDF + o0 + o) * SL + sq;
#pragma unroll
        for (int m = 0; m < 4; m++) {
            reinterpret_cast<uint4*>(g_sis_hi + off)[m] =
                make_uint4(uh[4 * m], uh[4 * m + 1], uh[4 * m + 2], uh[4 * m + 3]);
            reinterpret_cast<uint4*>(g_sis_lo + off)[m] =
                make_uint4(ul[4 * m], ul[4 * m + 1], ul[4 * m + 2], ul[4 * m + 3]);
        }
    }
    // ssi [b][s][i]: thread -> (s = tid/2, 32 o)
    {
        const int s = tid >> 1, oq = (tid & 1) * 32;
        uint32_t uh[16], ul[16];
#pragma unroll
        for (int m = 0; m < 16; m++) {
            float v0 = Cb[(oq + 2 * m) * 129 + s];
            float v1 = Cb[(oq + 2 * m + 1) * 129 + s];
            __nv_bfloat16 h0, l0, h1, l1; split2(v0, h0, l0); split2(v1, h1, l1);
            uh[m] = pack_bf2(h0, h1); ul[m] = pack_bf2(l0, l1);
        }
        size_t off = ((size_t)b * SL + s) * IDF + o0 + oq;
#pragma unroll
        for (int m = 0; m < 4; m++) {
            reinterpret_cast<uint4*>(g_ssi_hi + off)[m] =
                make_uint4(uh[4 * m], uh[4 * m + 1], uh[4 * m + 2], uh[4 * m + 3]);
            reinterpret_cast<uint4*>(g_ssi_lo + off)[m] =
                make_uint4(ul[4 * m], ul[4 * m + 1], ul[4 * m + 2], ul[4 * m + 3]);
        }
    }
}

// ---------------- fused attention: register softmax, no Cb ----------------
__global__ void __launch_bounds__(256, 2) attn_kernel(const float* __restrict__ input,
                                                      const int* __restrict__ mask,
                                                      float* __restrict__ wc,
                                                      float* __restrict__ aout) {
    extern __shared__ __align__(1024) char smem[];
    __shared__ float red[64][4];                    // cross-warp softmax reduce
    const int tid = threadIdx.x, lane = tid & 31, wp = tid >> 5;
    const int b = blockIdx.y, q0 = blockIdx.x * 64;
    uint32_t sb = smem_u32(smem);
    const uint32_t ASLOT = sb + ASLOTOFF;           // 3 x 8KB A conversion slots
    const uint32_t BATT  = sb + BATTOFF;            // 4 s-chunks x (hi 4KB | lo 4KB)

    // ---- phase 1: logits[q][s], K=768, 24 k=32 chunks ----
    const int wm1 = wp & 1, wn1 = wp >> 1;          // D 64(q) x 128(s)
    const __nv_bfloat16* sh_base = g_ssi_hi + (size_t)b * SL * IDF;
    const __nv_bfloat16* sl_base = g_ssi_lo + (size_t)b * SL * IDF;
    const int cq = tid & 63, cig = tid >> 6;        // conversion role
    const float* cbase = input + ((size_t)b * IDF + cig * 8) * QL + q0 + cq;
    const uint32_t coff = SW64((uint32_t)(cq * 64 + cig * 16));

    float acc[2][4][4];
    ZERO_ACC(acc);
    float cvt[8];

    auto ldgA = [&](int j) {
        const float* s = cbase + (size_t)(j * 32) * QL;
#pragma unroll
        for (int m = 0; m < 8; m++) cvt[m] = s[(size_t)m * QL];
    };
    auto stsA = [&](int j) {
        uint32_t h[4], l[4];
#pragma unroll
        for (int m = 0; m < 4; m++) {
            __nv_bfloat16 h0, l0, h1, l1;
            split2(cvt[2 * m], h0, l0); split2(cvt[2 * m + 1], h1, l1);
            h[m] = pack_bf2(h0, h1); l[m] = pack_bf2(l0, l1);
        }
        uint32_t A = ASLOT + (j % 3) * 8192;
        asm volatile("st.shared.v4.b32 [%0], {%1,%2,%3,%4};"
                     :: "r"(A + coff), "r"(h[0]), "r"(h[1]), "r"(h[2]), "r"(h[3]));
        asm volatile("st.shared.v4.b32 [%0], {%1,%2,%3,%4};"
                     :: "r"(A + 4096 + coff), "r"(l[0]), "r"(l[1]), "r"(l[2]), "r"(l[3]));
    };
    auto issueB = [&](int j) {
        uint32_t S = sb + (j % NSTG) * BSTAGE;
        cp64<128>(S,        sh_base + j * 32, IDF * 2, tid);
        cp64<128>(S + 8192, sl_base + j * 32, IDF * 2, tid);
        CP_COMMIT();
    };

    ldgA(0); stsA(0); ldgA(1);
    issueB(0); issueB(1);
#pragma unroll 1
    for (int j = 0; j < 24; j++) {
        if (j + 1 < 24) stsA(j + 1);
        if (j + 2 < 24) ldgA(j + 2);
        if (j < 23) CP_WAIT1(); else CP_WAIT0();
        __syncthreads();
        if (j + 2 < 24) issueB(j + 2);
        uint32_t S = sb + (j % NSTG) * BSTAGE;
        uint32_t A = ASLOT + (j % 3) * 8192;
        gemm_chunk(acc, A, A + 4096, S, S + 8192, wm1 * 32, wn1 * 32, lane);
    }
    __syncthreads();                                 // all warps done with slots

    // prefetch phase-3 stage 0/1 under the softmax
    const __nv_bfloat16* sish_base = g_sis_hi + (size_t)b * IDF * SL;
    const __nv_bfloat16* sisl_base = g_sis_lo + (size_t)b * IDF * SL;
    auto issue3 = [&](int c) {
        int t = c >> 2, kc = c & 3;
        uint32_t S = sb + (c % NSTG) * BSTAGE;
        const size_t base = (size_t)t * 128 * SL + kc * 32;
        cp64<128>(S,        sish_base + base, SL * 2, tid);
        cp64<128>(S + 8192, sisl_base + base, SL * 2, tid);
        CP_COMMIT();
    };
    issue3(0); issue3(1);

    // ---- phase 2: softmax entirely in registers ----
    // this thread's columns: s = wn1*32 + n*8 + (lane&3)*2 + vi; rows:
    // q = wm1*32 + mi*16 + (lane>>2) + h*8  (r-index = mi*2+h)
    {
        float mp[8];
#pragma unroll
        for (int n = 0; n < 4; n++)
#pragma unroll
            for (int vi = 0; vi < 2; vi++)
                mp[n * 2 + vi] = -10000.0f *
                    (float)mask[b * SL + wn1 * 32 + n * 8 + (lane & 3) * 2 + vi];

        float mx4[4];
#pragma unroll
        for (int mi = 0; mi < 2; mi++)
#pragma unroll
            for (int h = 0; h < 2; h++) {
                float mx = -1e30f;
#pragma unroll
                for (int n = 0; n < 4; n++)
#pragma unroll
                    for (int vi = 0; vi < 2; vi++) {
                        int v = h * 2 + vi;
                        acc[mi][n][v] += mp[n * 2 + vi];
                        mx = fmaxf(mx, acc[mi][n][v]);
                    }
                mx4[mi * 2 + h] = mx;
            }
#pragma unroll
        for (int r = 0; r < 4; r++) {
            mx4[r] = fmaxf(mx4[r], __shfl_xor_sync(0xffffffffu, mx4[r], 1));
            mx4[r] = fmaxf(mx4[r], __shfl_xor_sync(0xffffffffu, mx4[r], 2));
        }
        if ((lane & 3) == 0)
#pragma unroll
            for (int r = 0; r < 4; r++)
                red[wm1 * 32 + (r >> 1) * 16 + (lane >> 2) + (r & 1) * 8][wn1] = mx4[r];
        __syncthreads();
#pragma unroll
        for (int r = 0; r < 4; r++) {
            const float* rr = red[wm1 * 32 + (r >> 1) * 16 + (lane >> 2) + (r & 1) * 8];
            mx4[r] = fmaxf(fmaxf(rr[0], rr[1]), fmaxf(rr[2], rr[3]));
        }
        __syncthreads();                              // before red reuse for sums

        float sm4[4];
#pragma unroll
        for (int mi = 0; mi < 2; mi++)
#pragma unroll
            for (int h = 0; h < 2; h++) {
                float sum = 0.f;
#pragma unroll
                for (int n = 0; n < 4; n++)
#pragma unroll
                    for (int vi = 0; vi < 2; vi++) {
                        int v = h * 2 + vi;
                        float e = __expf(acc[mi][n][v] - mx4[mi * 2 + h]);
                        acc[mi][n][v] = e;
                        sum += e;
                    }
                sm4[mi * 2 + h] = sum;
            }
#pragma unroll
        for (int r = 0; r < 4; r++) {
            sm4[r] += __shfl_xor_sync(0xffffffffu, sm4[r], 1);
            sm4[r] += __shfl_xor_sync(0xffffffffu, sm4[r], 2);
        }
        if ((lane & 3) == 0)
#pragma unroll
            for (int r = 0; r < 4; r++)
                red[wm1 * 32 + (r >> 1) * 16 + (lane >> 2) + (r & 1) * 8][wn1] = sm4[r];
        __syncthreads();
#pragma unroll
        for (int r = 0; r < 4; r++) {
            const float* rr = red[wm1 * 32 + (r >> 1) * 16 + (lane >> 2) + (r & 1) * 8];
            sm4[r] = 1.0f / (rr[0] + rr[1] + rr[2] + rr[3]);
        }

        // scale; write attn_out (global) + BATT bf16 hi/lo (chunk = wn1)
        float* ao = aout + (size_t)b * SL * QL + q0;
        const uint32_t BH = BATT + wn1 * 8192, BL = BH + 4096;
#pragma unroll
        for (int mi = 0; mi < 2; mi++)
#pragma unroll
            for (int h = 0; h < 2; h++) {
                const float inv = sm4[mi * 2 + h];
                const int q = wm1 * 32 + mi * 16 + (lane >> 2) + h * 8;
#pragma unroll
                for (int n = 0; n < 4; n++) {
                    float e0 = acc[mi][n][h * 2 + 0] * inv;
                    float e1 = acc[mi][n][h * 2 + 1] * inv;
                    const int s0 = wn1 * 32 + n * 8 + (lane & 3) * 2;
                    ao[(size_t)s0 * QL + q]       = e0;
                    ao[(size_t)(s0 + 1) * QL + q] = e1;
                    __nv_bfloat16 h0, l0, h1, l1;
                    split2(e0, h0, l0); split2(e1, h1, l1);
                    uint32_t off = SW64((uint32_t)(q * 64 + (s0 & 31) * 2));
                    asm volatile("st.shared.b32 [%0], %1;"
                                 :: "r"(BH + off), "r"(pack_bf2(h0, h1)));
                    asm volatile("st.shared.b32 [%0], %1;"
                                 :: "r"(BL + off), "r"(pack_bf2(l0, l1)));
                }
            }
    }
    __syncthreads();   // BATT visible to all warps

    // ---- phase 3: wc[i][q] = sum_s sis[i][s]*attn[q][s]; 6 tiles x 4 chunks ----
    const int wm3 = wp >> 1, wn3 = wp & 1;          // D 128(i) x 64(q)
#pragma unroll 1
    for (int c = 0; c < 24; c++) {
        if (c < 23) CP_WAIT1(); else CP_WAIT0();
        __syncthreads();
        if (c + 2 < 24) issue3(c + 2);
        if ((c & 3) == 0) ZERO_ACC(acc);
        uint32_t S = sb + (c % NSTG) * BSTAGE;
        uint32_t BH = BATT + (c & 3) * 8192;
        gemm_chunk(acc, S, S + 8192, BH, BH + 4096, wm3 * 32, wn3 * 32, lane);
        if ((c & 3) == 3) {
            int t = c >> 2;
            float* w0 = wc + ((size_t)b * IDF + t * 128) * QL + q0;
#pragma unroll
            for (int m = 0; m < 2; m++)
#pragma unroll
                for (int n = 0; n < 4; n++) {
                    int r = wm3 * 32 + m * 16 + (lane >> 2);
                    int cc = wn3 * 32 + n * 8 + (lane & 3) * 2;
                    *reinterpret_cast<float2*>(w0 + (size_t)r * QL + cc) =
                        make_float2(acc[m][n][0], acc[m][n][1]);
                    *reinterpret_cast<float2*>(w0 + (size_t)(r + 8) * QL + cc) =
                        make_float2(acc[m][n][2], acc[m][n][3]);
                }
        }
    }
}

// ---------------------------------------------------------------------------
extern "C" void kernel_launch(void* const* d_in, const int* in_sizes, int n_in,
                              void* d_out, int out_size) {
    const float* input   = (const float*)d_in[0];
    const float* context = (const float*)d_in[1];
    const int*   mask    = (const int*)d_in[2];
    const float* w_conv  = (const float*)d_in[3];

    float* wc   = (float*)d_out;
    float* aout = wc + (size_t)NB * IDF * QL;

    conv_w_kernel<<<IDF * CDF / 4 / 256, 256>>>(w_conv);
    trans_ctx_kernel<<<dim3(SL / 32, CDF / 32, NB), dim3(32, 8)>>>(context);

    const int smem_proj = NSTG * PSTAGE;                    // 73728
    cudaFuncSetAttribute(proj_kernel, cudaFuncAttributeMaxDynamicSharedMemorySize,
                         smem_proj);
    proj_kernel<<<dim3(IDF / 64, NB), 256, smem_proj>>>();

    cudaFuncSetAttribute(attn_kernel, cudaFuncAttributeMaxDynamicSharedMemorySize,
                         ATTN_SMEM);                        // 106496
    attn_kernel<<<dim3(QL / 64, NB), 256, ATTN_SMEM>>>(input, mask, wc, aout);
}